// round 15
// baseline (speedup 1.0000x reference)
#include <cuda_runtime.h>
#include <cuda_bf16.h>
#include <cstdint>

// Problem constants
#define Tn   1024
#define Bn   64
#define Dn   32
#define Hn   512
#define NG   4              // independent batch groups
#define GC   32             // CTAs per group
#define NCTA 128
#define NTHR 256

// Device-global scratch
// h history, packed u32: low16 = bf16(hi), high16 = bf16(lo)
__device__ unsigned g_hpk[(size_t)(Tn + 1) * NG * 16 * 512];  // [t][g][b][k]
__device__ unsigned g_xpk[(size_t)Tn * NG * 16 * 32];         // [t][g][b][d]
__device__ __align__(128) unsigned g_flags[NCTA * 32];        // 1 flag / 128B line

// SMEM layout (bytes)
#define OFF_BIAS  0                         // 64 floats
#define OFF_A     256
#define A_BYTES   (8 * 34 * 512)            // 139264: [rs 8][ksg 34][512B frag]
#define OFF_BHI   (OFF_A + A_BYTES)         // 139520
#define TILE_B    17408                     // 34 ksteps x 2 nt x 256B
#define OFF_BLO   (OFF_BHI + TILE_B)        // 156928
#define OFF_R     (OFF_BLO + TILE_B)        // 174336: 6 parts x 64 r x 20 floats
#define SMEM_TOTAL (OFF_R + 6 * 64 * 20 * 4)   // 205056

#define L2E 1.4426950408889634f

__device__ __forceinline__ float ex2f(float x) {
    float y; asm("ex2.approx.ftz.f32 %0, %1;" : "=f"(y) : "f"(x)); return y;
}
__device__ __forceinline__ float rcpf(float x) {
    float y; asm("rcp.approx.ftz.f32 %0, %1;" : "=f"(y) : "f"(x)); return y;
}
// pack fp32 -> {bf16 hi | bf16 lo << 16}
__device__ __forceinline__ unsigned packhl(float v) {
    unsigned hb = (unsigned)__bfloat16_as_ushort(__float2bfloat16(v));
    float hf = __uint_as_float(hb << 16);
    unsigned lb = (unsigned)__bfloat16_as_ushort(__float2bfloat16(v - hf));
    return hb | (lb << 16);
}
__device__ __forceinline__ void sts64(uint32_t a, uint32_t x, uint32_t y) {
    asm volatile("st.shared.v2.b32 [%0], {%1,%2};" :: "r"(a), "r"(x), "r"(y));
}
__device__ __forceinline__ void sts128v(uint32_t a, uint32_t x, uint32_t y,
                                        uint32_t z, uint32_t w) {
    asm volatile("st.shared.v4.b32 [%0], {%1,%2,%3,%4};"
                 :: "r"(a), "r"(x), "r"(y), "r"(z), "r"(w));
}
__device__ __forceinline__ void lds64(uint32_t& x, uint32_t& y, uint32_t a) {
    asm volatile("ld.shared.v2.b32 {%0,%1}, [%2];" : "=r"(x), "=r"(y) : "r"(a));
}
__device__ __forceinline__ void lds128(uint32_t* r, uint32_t a) {
    asm volatile("ld.shared.v4.b32 {%0,%1,%2,%3}, [%4];"
                 : "=r"(r[0]), "=r"(r[1]), "=r"(r[2]), "=r"(r[3]) : "r"(a));
}
__device__ __forceinline__ void poll_flag_sleep(const unsigned* fptr,
                                                unsigned tgt) {
    for (;;) {
        unsigned v;
        asm volatile("ld.acquire.gpu.global.u32 %0, [%1];"
                     : "=r"(v) : "l"(fptr) : "memory");
        if (!__any_sync(0xFFFFFFFFu, (int)(v - tgt) < 0)) break;
        __nanosleep(32);
    }
}
__device__ __forceinline__ void spin1(const unsigned* fptr, unsigned tgt) {
    unsigned v;
    do {
        asm volatile("ld.acquire.gpu.global.u32 %0, [%1];"
                     : "=r"(v) : "l"(fptr) : "memory");
    } while ((int)(v - tgt) < 0);
}
__device__ __forceinline__ void publish(unsigned* flag, unsigned val) {
    asm volatile("st.release.gpu.global.u32 [%0], %1;"
                 :: "l"(flag), "r"(val) : "memory");
}
// m16n8k16 bf16 mma, fp32 acc (HMMA, valid on base sm_103 target)
#define MMA16816(C, A, B0, B1)                                               \
    asm volatile(                                                            \
        "mma.sync.aligned.m16n8k16.row.col.f32.bf16.bf16.f32 "               \
        "{%0,%1,%2,%3}, {%4,%5,%6,%7}, {%8,%9}, {%0,%1,%2,%3};"              \
        : "+f"((C)[0]), "+f"((C)[1]), "+f"((C)[2]), "+f"((C)[3])             \
        : "r"((A)[0]), "r"((A)[1]), "r"((A)[2]), "r"((A)[3]),                \
          "r"(B0), "r"(B1))

// bf16 bits of A'(row, col): row<64 -> hi(W[row]), row>=64 -> lo(W[row-64])
__device__ __forceinline__ unsigned wbits(const float* __restrict__ Whh,
                                          const float* __restrict__ Wih,
                                          int c, int row, int col) {
    int r = row & 63;
    int n = (r >> 4) * Hn + c * 16 + (r & 15);
    float w = (col < 512) ? Whh[(size_t)n * Hn + col]
                          : Wih[n * Dn + (col - 512)];
    unsigned hb = (unsigned)__bfloat16_as_ushort(__float2bfloat16(w));
    if (row < 64) return hb;
    float hf = __uint_as_float(hb << 16);
    return (unsigned)__bfloat16_as_ushort(__float2bfloat16(w - hf));
}

extern __shared__ char smem[];

// ===========================================================================
__global__ void __launch_bounds__(NTHR, 1) lstm_hmma_kernel(
    const float* __restrict__ x,      // (B, D, T)
    const float* __restrict__ W_ih,   // (4H, D)
    const float* __restrict__ W_hh,   // (4H, H)
    const float* __restrict__ b_ih,   // (4H,)
    const float* __restrict__ b_hh,   // (4H,)
    const float* __restrict__ cw,     // (1, H, 1)
    const float* __restrict__ cb,     // (1,)
    float* __restrict__ out)          // (B, 1, T)
{
    const int tid  = threadIdx.x;
    const int cta  = blockIdx.x;
    const int g    = cta >> 5;
    const int c    = cta & 31;
    const int wid  = tid >> 5, lane = tid & 31;
    const int ms   = wid & 3;          // M-slice (pass1 rows 32ms..+32)
    const int kh   = wid >> 2;         // K-half (17 ksteps each)
    const int fg   = lane >> 2;        // fragment group id (row in tile)
    const int ft   = lane & 3;         // fragment thread pair (col)
    const uint32_t sb = (uint32_t)__cvta_generic_to_shared(smem);
    float* smf     = (float*)smem;
    float* sm_bias = smf + OFF_BIAS / 4;

    const unsigned base = g_flags[cta * 32];

    // ---- preamble: pack x (B,D,T) -> g_xpk[t][g][b][d]; this CTA's 1/128 ----
    {
        const float4* x4 = (const float4*)x;
        for (int i = tid; i < 4096; i += NTHR) {
            int idx4 = cta * 4096 + i;
            float4 v = __ldcg(x4 + idx4);
            int t0 = (idx4 & 255) * 4;
            int d  = (idx4 >> 8) & 31;
            int b  = idx4 >> 13;
            unsigned* dst = g_xpk + ((b >> 4) * 16 + (b & 15)) * 32 + d;
            dst[(size_t)(t0 + 0) * 2048] = packhl(v.x);
            dst[(size_t)(t0 + 1) * 2048] = packhl(v.y);
            dst[(size_t)(t0 + 2) * 2048] = packhl(v.z);
            dst[(size_t)(t0 + 3) * 2048] = packhl(v.w);
        }
    }
    // zero own h(0)
    g_hpk[((size_t)g * 16 + (tid >> 4)) * 512 + c * 16 + (tid & 15)] = 0u;
    if (tid < 64) {
        int n = (tid >> 4) * Hn + c * 16 + (tid & 15);
        sm_bias[tid] = b_ih[n] + b_hh[n];
    }

    // ---- A fragments into SMEM, fragment-linear: [rs 8][ksg 34][lane 16B] ----
    for (int idx = tid; idx < 8 * 34 * 32; idx += NTHR) {
        int l2  = idx & 31;
        int ksg = (idx >> 5) % 34;
        int rs  = idx / (34 * 32);
        int f2 = l2 >> 2, t2 = l2 & 3;
        int row = 16 * rs + f2;
        int col = 16 * ksg + 2 * t2;
        unsigned a0 = wbits(W_hh, W_ih, c, row,     col)     |
                      (wbits(W_hh, W_ih, c, row,     col + 1) << 16);
        unsigned a1 = wbits(W_hh, W_ih, c, row + 8, col)     |
                      (wbits(W_hh, W_ih, c, row + 8, col + 1) << 16);
        unsigned a2 = wbits(W_hh, W_ih, c, row,     col + 8) |
                      (wbits(W_hh, W_ih, c, row,     col + 9) << 16);
        unsigned a3 = wbits(W_hh, W_ih, c, row + 8, col + 8) |
                      (wbits(W_hh, W_ih, c, row + 8, col + 9) << 16);
        sts128v(sb + OFF_A + (unsigned)idx * 16u, a0, a1, a2, a3);
    }

    __syncthreads();
    if (tid == 0) publish(&g_flags[cta * 32], base + 1);
    if (tid < 128) poll_flag_sleep(&g_flags[tid * 32], base + 1);
    __syncthreads();

    // epilogue mapping
    const int ebl = tid & 15, ehl = tid >> 4;
    float c_reg = 0.f;

    // staging: thread stages source ksteps sks0, sks1
    const int sks0 = tid >> 4;            // 0..15
    const int sks1 = 16 + (tid >> 4);     // 16..31

    // A/B SMEM bases for this warp
    const uint32_t a1b_0 = sb + OFF_A + ((2 * ms + 0) * 34 + kh * 17) * 512 + lane * 16;
    const uint32_t a1b_1 = sb + OFF_A + ((2 * ms + 1) * 34 + kh * 17) * 512 + lane * 16;
    const uint32_t a2b   = sb + OFF_A + (ms * 34 + kh * 17) * 512 + lane * 16;
    const uint32_t bhib  = sb + OFF_BHI + (kh * 17) * 512 + lane * 8;
    const uint32_t blob  = sb + OFF_BLO + (kh * 17) * 512 + lane * 8;

    for (int t = 0; t < Tn; ++t) {
        // ---- poll the two h-source flags this thread stages ----
        {
            const unsigned tgt = base + (unsigned)t + 1;
            spin1(&g_flags[(g * 32 + sks0) * 32], tgt);
            spin1(&g_flags[(g * 32 + sks1) * 32], tgt);
            __syncwarp();
        }
        // ---- stage B tiles (fragment-linear, split hi/lo) ----
        {
            int na = (tid < 32) ? 3 : 2;
            #pragma unroll
            for (int ai = 0; ai < 3; ++ai) {
                if (ai >= na) break;
                int aa = tid + ai * 256;
                int ks = aa >> 4, b = aa & 15;
                const uint4* src;
                if (ks < 32)
                    src = (const uint4*)(g_hpk + ((size_t)t * NG + g) * 8192 +
                                         b * 512 + ks * 16);
                else
                    src = (const uint4*)(g_xpk + ((size_t)t * NG + g) * 512 +
                                         b * 32 + (ks - 32) * 16);
                uint4 q0 = __ldcg(src + 0), q1 = __ldcg(src + 1);
                uint4 q2 = __ldcg(src + 2), q3 = __ldcg(src + 3);
                unsigned w[16] = {q0.x, q0.y, q0.z, q0.w, q1.x, q1.y, q1.z, q1.w,
                                  q2.x, q2.y, q2.z, q2.w, q3.x, q3.y, q3.z, q3.w};
                int nt = b >> 3, g2 = b & 7;
                uint32_t bh = sb + OFF_BHI + (ks * 2 + nt) * 256 + g2 * 32;
                uint32_t bl = sb + OFF_BLO + (ks * 2 + nt) * 256 + g2 * 32;
                #pragma unroll
                for (int t4 = 0; t4 < 4; ++t4) {
                    unsigned h0 = __byte_perm(w[2 * t4],     w[2 * t4 + 1], 0x5410);
                    unsigned h1 = __byte_perm(w[2 * t4 + 8], w[2 * t4 + 9], 0x5410);
                    sts64(bh + t4 * 8, h0, h1);
                    unsigned l0 = __byte_perm(w[2 * t4],     w[2 * t4 + 1], 0x7632);
                    unsigned l1 = __byte_perm(w[2 * t4 + 8], w[2 * t4 + 9], 0x7632);
                    sts64(bl + t4 * 8, l0, l1);
                }
            }
        }
        __syncthreads();

        // ---- pass 1: (A_hi|A_lo rows 32ms..+32) x B_hi, 17 ksteps ----
        float acc[2][2][4];
        #pragma unroll
        for (int mt = 0; mt < 2; ++mt)
            #pragma unroll
            for (int nt = 0; nt < 2; ++nt)
                #pragma unroll
                for (int j = 0; j < 4; ++j) acc[mt][nt][j] = 0.f;

        #pragma unroll
        for (int ks = 0; ks < 17; ++ks) {
            uint32_t af0[4], af1[4];
            lds128(af0, a1b_0 + ks * 512);
            lds128(af1, a1b_1 + ks * 512);
            uint32_t b00, b01, b10, b11;
            lds64(b00, b01, bhib + ks * 512);
            lds64(b10, b11, bhib + ks * 512 + 256);
            MMA16816(acc[0][0], af0, b00, b01);
            MMA16816(acc[0][1], af0, b10, b11);
            MMA16816(acc[1][0], af1, b00, b01);
            MMA16816(acc[1][1], af1, b10, b11);
        }

        // ---- pass 2: A_hi rows 16ms..+16 x B_lo (hi*lo term) ----
        float acc2[2][4];
        #pragma unroll
        for (int nt = 0; nt < 2; ++nt)
            #pragma unroll
            for (int j = 0; j < 4; ++j) acc2[nt][j] = 0.f;

        #pragma unroll
        for (int ks = 0; ks < 17; ++ks) {
            uint32_t af2[4];
            lds128(af2, a2b + ks * 512);
            uint32_t b00, b01, b10, b11;
            lds64(b00, b01, blob + ks * 512);
            lds64(b10, b11, blob + ks * 512 + 256);
            MMA16816(acc2[0], af2, b00, b01);
            MMA16816(acc2[1], af2, b10, b11);
        }

        // ---- store partials ----
        {
            // pass1: part = kh*2 + (ms>>1), rows r = 32(ms&1)+16mt+fg (+8)
            int part = kh * 2 + (ms >> 1);
            float* rp = smf + OFF_R / 4 + part * 64 * 20;
            int rbase = 32 * (ms & 1) + fg;
            #pragma unroll
            for (int mt = 0; mt < 2; ++mt) {
                #pragma unroll
                for (int nt = 0; nt < 2; ++nt) {
                    int R = rbase + 16 * mt;
                    int col = 8 * nt + 2 * ft;
                    *(float2*)(rp + R * 20 + col) =
                        make_float2(acc[mt][nt][0], acc[mt][nt][1]);
                    *(float2*)(rp + (R + 8) * 20 + col) =
                        make_float2(acc[mt][nt][2], acc[mt][nt][3]);
                }
            }
            // pass2: part = 4 + kh, rows r = 16ms+fg (+8)
            float* rp2 = smf + OFF_R / 4 + (4 + kh) * 64 * 20;
            int r2 = 16 * ms + fg;
            #pragma unroll
            for (int nt = 0; nt < 2; ++nt) {
                int col = 8 * nt + 2 * ft;
                *(float2*)(rp2 + r2 * 20 + col) =
                    make_float2(acc2[nt][0], acc2[nt][1]);
                *(float2*)(rp2 + (r2 + 8) * 20 + col) =
                    make_float2(acc2[nt][2], acc2[nt][3]);
            }
        }
        __syncthreads();

        // ---- reduce 6 partials -> gates in sm_r[0] ----
        {
            int r = tid >> 2, b4 = tid & 3;
            float* rp0 = smf + OFF_R / 4;
            float4 s0 = *(float4*)(rp0 + (0 * 64 + r) * 20 + b4 * 4);
            float4 s1 = *(float4*)(rp0 + (1 * 64 + r) * 20 + b4 * 4);
            float4 s2 = *(float4*)(rp0 + (2 * 64 + r) * 20 + b4 * 4);
            float4 s3 = *(float4*)(rp0 + (3 * 64 + r) * 20 + b4 * 4);
            float4 s4 = *(float4*)(rp0 + (4 * 64 + r) * 20 + b4 * 4);
            float4 s5 = *(float4*)(rp0 + (5 * 64 + r) * 20 + b4 * 4);
            *(float4*)(rp0 + r * 20 + b4 * 4) =
                make_float4(s0.x + s1.x + s2.x + s3.x + s4.x + s5.x,
                            s0.y + s1.y + s2.y + s3.y + s4.y + s5.y,
                            s0.z + s1.z + s2.z + s3.z + s4.z + s5.z,
                            s0.w + s1.w + s2.w + s3.w + s4.w + s5.w);
        }
        __syncthreads();

        // ---- LSTM cell epilogue ----
        {
            const float* gb = smf + OFF_R / 4;
            float xi = gb[( 0 + ehl) * 20 + ebl] + sm_bias[ 0 + ehl];
            float xf = gb[(16 + ehl) * 20 + ebl] + sm_bias[16 + ehl];
            float xg = gb[(32 + ehl) * 20 + ebl] + sm_bias[32 + ehl];
            float xo = gb[(48 + ehl) * 20 + ebl] + sm_bias[48 + ehl];
            float ei = ex2f(-xi * L2E);
            float ef = ex2f(-xf * L2E);
            float eo = ex2f(-xo * L2E);
            float eg = ex2f(-2.f * xg * L2E);
            float di = 1.f + ei, df = 1.f + ef, dc = 1.f + eo, dg = 1.f + eg;
            float q0 = rcpf(di * df);
            float ii = q0 * df, ff = q0 * di;
            float q1 = rcpf(dc * dg);
            float oo = q1 * dg;
            float tg = (1.f - eg) * (q1 * dc);
            c_reg = ff * c_reg + ii * tg;
            float ec = ex2f(-2.f * c_reg * L2E);
            float tc = (1.f - ec) * rcpf(1.f + ec);
            float h  = oo * tc;
            g_hpk[(((size_t)(t + 1) * NG + g) * 16 + ebl) * 512 + c * 16 + ehl] =
                packhl(h);
        }
        __syncthreads();
        if (tid == 0) publish(&g_flags[cta * 32], base + (unsigned)t + 2);
    }

    // ================= conv tail =================
    if (tid < 32)
        poll_flag_sleep(&g_flags[(g * 32 + tid) * 32], base + Tn + 1);
    __syncthreads();

    float* scw  = smf + OFF_BHI / 4;      // reuse B tiles
    float* sred = scw + 512;
    for (int i = tid; i < Hn; i += NTHR) scw[i] = cw[i];
    const float cbv = cb[0];
    __syncthreads();

    const int cb2 = tid >> 4, cs = tid & 15;
    for (int j = 0; j < Tn / GC; ++j) {
        int t = c * (Tn / GC) + j;
        const unsigned* hp =
            g_hpk + (((size_t)(t + 1) * NG + g) * 16 + cb2) * 512 + cs * 32;
        float acc = 0.f;
        #pragma unroll 8
        for (int h = 0; h < 32; ++h) {
            unsigned w = __ldcg(hp + h);
            float hv = __uint_as_float(w << 16) +
                       __uint_as_float(w & 0xFFFF0000u);
            acc += hv * scw[cs * 32 + h];
        }
        sred[tid] = acc;
        __syncthreads();
        if (tid < 16) {
            float s = cbv;
            #pragma unroll
            for (int q = 0; q < 16; ++q) s += sred[tid * 16 + q];
            out[(size_t)(g * 16 + tid) * Tn + t] = s;
        }
        __syncthreads();
    }
}

// ---------------------------------------------------------------------------
extern "C" void kernel_launch(void* const* d_in, const int* in_sizes, int n_in,
                              void* d_out, int out_size)
{
    const float* x    = (const float*)d_in[0];
    const float* W_ih = (const float*)d_in[1];
    const float* W_hh = (const float*)d_in[2];
    const float* b_ih = (const float*)d_in[3];
    const float* b_hh = (const float*)d_in[4];
    const float* cw   = (const float*)d_in[5];
    const float* cb   = (const float*)d_in[6];
    float* out = (float*)d_out;

    cudaFuncSetAttribute(lstm_hmma_kernel,
                         cudaFuncAttributeMaxDynamicSharedMemorySize, SMEM_TOTAL);
    lstm_hmma_kernel<<<NCTA, NTHR, SMEM_TOTAL>>>(x, W_ih, W_hh, b_ih, b_hh,
                                                 cw, cb, out);
}

// round 16
// speedup vs baseline: 1.2646x; 1.2646x over previous
#include <cuda_runtime.h>
#include <cuda_bf16.h>
#include <cstdint>

// Problem constants
#define Tn   1024
#define Bn   64
#define Dn   32
#define Hn   512
#define NG   4              // independent batch groups
#define GC   32             // CTAs per group
#define NCTA 128
#define NTHR 256

// Device-global scratch
// h history, packed u32: low16 = bf16(hi), high16 = bf16(lo)
__device__ unsigned g_hpk[(size_t)(Tn + 1) * NG * 16 * 512];  // [t][g][b][k]
__device__ unsigned g_xpk[(size_t)Tn * NG * 16 * 32];         // [t][g][b][d]
__device__ __align__(128) unsigned g_flags[NCTA * 32];        // 1 flag / 128B line

// SMEM layout (bytes)
#define OFF_BIAS  0                     // 64 floats
#define OFF_BHI   256
#define TILE_B    17408                 // 34 ksteps x 2 nt x 64 words x 4B
#define OFF_BLO   (OFF_BHI + TILE_B)    // 17664
#define OFF_R     (OFF_BLO + TILE_B)    // 35072: 4 parts x 64 r x 20 floats
#define SMEM_TOTAL (OFF_R + 4 * 64 * 20 * 4)   // 55552

#define L2E 1.4426950408889634f

__device__ __forceinline__ float ex2f(float x) {
    float y; asm("ex2.approx.ftz.f32 %0, %1;" : "=f"(y) : "f"(x)); return y;
}
__device__ __forceinline__ float rcpf(float x) {
    float y; asm("rcp.approx.ftz.f32 %0, %1;" : "=f"(y) : "f"(x)); return y;
}
// pack fp32 -> {bf16 hi | bf16 lo << 16}
__device__ __forceinline__ unsigned packhl(float v) {
    unsigned hb = (unsigned)__bfloat16_as_ushort(__float2bfloat16(v));
    float hf = __uint_as_float(hb << 16);
    unsigned lb = (unsigned)__bfloat16_as_ushort(__float2bfloat16(v - hf));
    return hb | (lb << 16);
}
__device__ __forceinline__ void sts64(uint32_t a, uint32_t x, uint32_t y) {
    asm volatile("st.shared.v2.b32 [%0], {%1,%2};" :: "r"(a), "r"(x), "r"(y));
}
__device__ __forceinline__ void lds64(uint32_t& x, uint32_t& y, uint32_t a) {
    asm volatile("ld.shared.v2.b32 {%0,%1}, [%2];" : "=r"(x), "=r"(y) : "r"(a));
}
__device__ __forceinline__ void poll_flag_sleep(const unsigned* fptr,
                                                unsigned tgt) {
    for (;;) {
        unsigned v;
        asm volatile("ld.acquire.gpu.global.u32 %0, [%1];"
                     : "=r"(v) : "l"(fptr) : "memory");
        if (!__any_sync(0xFFFFFFFFu, (int)(v - tgt) < 0)) break;
        __nanosleep(32);
    }
}
__device__ __forceinline__ void publish(unsigned* flag, unsigned val) {
    asm volatile("st.release.gpu.global.u32 [%0], %1;"
                 :: "l"(flag), "r"(val) : "memory");
}
// m16n8k16 bf16 mma, fp32 acc (HMMA, valid on base sm_103 target)
#define MMA16816(C, A, B0, B1)                                               \
    asm volatile(                                                            \
        "mma.sync.aligned.m16n8k16.row.col.f32.bf16.bf16.f32 "               \
        "{%0,%1,%2,%3}, {%4,%5,%6,%7}, {%8,%9}, {%0,%1,%2,%3};"              \
        : "+f"((C)[0]), "+f"((C)[1]), "+f"((C)[2]), "+f"((C)[3])             \
        : "r"((A)[0]), "r"((A)[1]), "r"((A)[2]), "r"((A)[3]),                \
          "r"(B0), "r"(B1))

// bf16 bits of A'(row, col): row<64 -> hi(W[row]), row>=64 -> lo(W[row-64])
__device__ __forceinline__ unsigned wbits(const float* __restrict__ Whh,
                                          const float* __restrict__ Wih,
                                          int c, int row, int col) {
    int r = row & 63;
    int n = (r >> 4) * Hn + c * 16 + (r & 15);
    float w = (col < 512) ? Whh[(size_t)n * Hn + col]
                          : Wih[n * Dn + (col - 512)];
    unsigned hb = (unsigned)__bfloat16_as_ushort(__float2bfloat16(w));
    if (row < 64) return hb;
    float hf = __uint_as_float(hb << 16);
    return (unsigned)__bfloat16_as_ushort(__float2bfloat16(w - hf));
}

extern __shared__ char smem[];

// ===========================================================================
__global__ void __launch_bounds__(NTHR, 1) lstm_hmma_kernel(
    const float* __restrict__ x,      // (B, D, T)
    const float* __restrict__ W_ih,   // (4H, D)
    const float* __restrict__ W_hh,   // (4H, H)
    const float* __restrict__ b_ih,   // (4H,)
    const float* __restrict__ b_hh,   // (4H,)
    const float* __restrict__ cw,     // (1, H, 1)
    const float* __restrict__ cb,     // (1,)
    float* __restrict__ out)          // (B, 1, T)
{
    const int tid  = threadIdx.x;
    const int cta  = blockIdx.x;
    const int g    = cta >> 5;
    const int c    = cta & 31;
    const int wid  = tid >> 5, lane = tid & 31;
    const int ms   = wid & 3;          // M-slice: 16 rows within hi / lo
    const int kh   = wid >> 2;         // K-half (17 ksteps each)
    const int fg   = lane >> 2;        // fragment group id
    const int ft   = lane & 3;         // fragment thread-in-group
    const uint32_t sb = (uint32_t)__cvta_generic_to_shared(smem);
    float* smf     = (float*)smem;
    float* sm_bias = smf + OFF_BIAS / 4;

    const unsigned base = g_flags[cta * 32];

    // ---- preamble: pack x (B,D,T) -> g_xpk[t][g][b][d]; this CTA's 1/128 ----
    {
        const float4* x4 = (const float4*)x;
        for (int i = tid; i < 4096; i += NTHR) {
            int idx4 = cta * 4096 + i;
            float4 v = __ldcg(x4 + idx4);
            int t0 = (idx4 & 255) * 4;
            int d  = (idx4 >> 8) & 31;
            int b  = idx4 >> 13;
            unsigned* dst = g_xpk + ((b >> 4) * 16 + (b & 15)) * 32 + d;
            dst[(size_t)(t0 + 0) * 2048] = packhl(v.x);
            dst[(size_t)(t0 + 1) * 2048] = packhl(v.y);
            dst[(size_t)(t0 + 2) * 2048] = packhl(v.z);
            dst[(size_t)(t0 + 3) * 2048] = packhl(v.w);
        }
    }
    // zero own h(0)
    g_hpk[((size_t)g * 16 + (tid >> 4)) * 512 + c * 16 + (tid & 15)] = 0u;
    if (tid < 64) {
        int n = (tid >> 4) * Hn + c * 16 + (tid & 15);
        sm_bias[tid] = b_ih[n] + b_hh[n];
    }

    // ---- A fragments into registers: a[mt][ks][rg] ----
    // mt=0: hi rows 16ms..16ms+15; mt=1: lo rows 64+16ms..64+16ms+15
    unsigned a[2][17][4];
    #pragma unroll
    for (int mt = 0; mt < 2; ++mt) {
        #pragma unroll
        for (int ks = 0; ks < 17; ++ks) {
            #pragma unroll
            for (int rg = 0; rg < 4; ++rg) {
                int row = 64 * mt + 16 * ms + fg + (rg & 1) * 8;
                int col = 272 * kh + 16 * ks + 2 * ft + (rg >> 1) * 8;
                unsigned w0 = wbits(W_hh, W_ih, c, row, col);
                unsigned w1 = wbits(W_hh, W_ih, c, row, col + 1);
                a[mt][ks][rg] = w0 | (w1 << 16);
            }
        }
    }

    __syncthreads();
    if (tid == 0) publish(&g_flags[cta * 32], base + 1);
    if (tid < 128) poll_flag_sleep(&g_flags[tid * 32], base + 1);
    __syncthreads();

    // epilogue mapping
    const int ebl = tid & 15, ehl = tid >> 4;
    float c_reg = 0.f;

    // staging: thread stages source ksteps sks0, sks1
    const int sks0 = tid >> 4;            // 0..15
    const int sks1 = 16 + (tid >> 4);     // 16..31
    const unsigned* fp0 = &g_flags[(g * 32 + sks0) * 32];
    const unsigned* fp1 = &g_flags[(g * 32 + sks1) * 32];

    const uint32_t bhib = sb + OFF_BHI + (kh * 17) * 512 + lane * 8;
    const uint32_t blob = sb + OFF_BLO + (kh * 17) * 512 + lane * 8;

    for (int t = 0; t < Tn; ++t) {
        // ---- stage x slice first (no flag dependency) ----
        if (tid < 32) {
            int aa = tid + 512;
            int ks = aa >> 4, b = aa & 15;        // ks in {32,33}
            const uint4* src = (const uint4*)
                (g_xpk + ((size_t)t * NG + g) * 512 + b * 32 + (ks - 32) * 16);
            uint4 q0 = __ldcg(src + 0), q1 = __ldcg(src + 1);
            uint4 q2 = __ldcg(src + 2), q3 = __ldcg(src + 3);
            unsigned w[16] = {q0.x, q0.y, q0.z, q0.w, q1.x, q1.y, q1.z, q1.w,
                              q2.x, q2.y, q2.z, q2.w, q3.x, q3.y, q3.z, q3.w};
            int nt = b >> 3, g2 = b & 7;
            uint32_t bh = sb + OFF_BHI + (ks * 2 + nt) * 256 + g2 * 32;
            uint32_t bl = sb + OFF_BLO + (ks * 2 + nt) * 256 + g2 * 32;
            #pragma unroll
            for (int t4 = 0; t4 < 4; ++t4) {
                sts64(bh + t4 * 8,
                      __byte_perm(w[2 * t4],     w[2 * t4 + 1], 0x5410),
                      __byte_perm(w[2 * t4 + 8], w[2 * t4 + 9], 0x5410));
                sts64(bl + t4 * 8,
                      __byte_perm(w[2 * t4],     w[2 * t4 + 1], 0x7632),
                      __byte_perm(w[2 * t4 + 8], w[2 * t4 + 9], 0x7632));
            }
        }
        // ---- fused dual-flag poll ----
        {
            const unsigned tgt = base + (unsigned)t + 1;
            unsigned v0, v1;
            do {
                asm volatile("ld.acquire.gpu.global.u32 %0, [%1];"
                             : "=r"(v0) : "l"(fp0) : "memory");
                asm volatile("ld.acquire.gpu.global.u32 %0, [%1];"
                             : "=r"(v1) : "l"(fp1) : "memory");
            } while (((int)(v0 - tgt) < 0) | ((int)(v1 - tgt) < 0));
            __syncwarp();
        }
        // ---- stage h tiles (2 slices per thread, split hi/lo) ----
        #pragma unroll
        for (int ai = 0; ai < 2; ++ai) {
            int aa = tid + ai * 256;
            int ks = aa >> 4, b = aa & 15;
            const uint4* src = (const uint4*)
                (g_hpk + ((size_t)t * NG + g) * 8192 + b * 512 + ks * 16);
            uint4 q0 = __ldcg(src + 0), q1 = __ldcg(src + 1);
            uint4 q2 = __ldcg(src + 2), q3 = __ldcg(src + 3);
            unsigned w[16] = {q0.x, q0.y, q0.z, q0.w, q1.x, q1.y, q1.z, q1.w,
                              q2.x, q2.y, q2.z, q2.w, q3.x, q3.y, q3.z, q3.w};
            int nt = b >> 3, g2 = b & 7;
            uint32_t bh = sb + OFF_BHI + (ks * 2 + nt) * 256 + g2 * 32;
            uint32_t bl = sb + OFF_BLO + (ks * 2 + nt) * 256 + g2 * 32;
            #pragma unroll
            for (int t4 = 0; t4 < 4; ++t4) {
                sts64(bh + t4 * 8,
                      __byte_perm(w[2 * t4],     w[2 * t4 + 1], 0x5410),
                      __byte_perm(w[2 * t4 + 8], w[2 * t4 + 9], 0x5410));
                sts64(bl + t4 * 8,
                      __byte_perm(w[2 * t4],     w[2 * t4 + 1], 0x7632),
                      __byte_perm(w[2 * t4 + 8], w[2 * t4 + 9], 0x7632));
            }
        }
        __syncthreads();

        // ---- pass 1: B_hi x (A_hi + A_lo), 17 ksteps ----
        float acc[2][2][4];
        #pragma unroll
        for (int mt = 0; mt < 2; ++mt)
            #pragma unroll
            for (int nt = 0; nt < 2; ++nt)
                #pragma unroll
                for (int j = 0; j < 4; ++j) acc[mt][nt][j] = 0.f;

        #pragma unroll
        for (int ks = 0; ks < 17; ++ks) {
            uint32_t b00, b01, b10, b11;
            lds64(b00, b01, bhib + ks * 512);
            lds64(b10, b11, bhib + ks * 512 + 256);
            MMA16816(acc[0][0], a[0][ks], b00, b01);
            MMA16816(acc[0][1], a[0][ks], b10, b11);
            MMA16816(acc[1][0], a[1][ks], b00, b01);
            MMA16816(acc[1][1], a[1][ks], b10, b11);
        }
        // ---- pass 2: B_lo x A_hi only (drop lo*lo) ----
        #pragma unroll
        for (int ks = 0; ks < 17; ++ks) {
            uint32_t b00, b01, b10, b11;
            lds64(b00, b01, blob + ks * 512);
            lds64(b10, b11, blob + ks * 512 + 256);
            MMA16816(acc[0][0], a[0][ks], b00, b01);
            MMA16816(acc[0][1], a[0][ks], b10, b11);
        }

        // ---- store partials: part = kh*2 + mt, rows 16ms+fg (+8) ----
        {
            int rbase = 16 * ms + fg;
            #pragma unroll
            for (int mt = 0; mt < 2; ++mt) {
                float* rp = smf + OFF_R / 4 + (kh * 2 + mt) * 64 * 20;
                #pragma unroll
                for (int nt = 0; nt < 2; ++nt) {
                    int col = 8 * nt + 2 * ft;
                    *(float2*)(rp + rbase * 20 + col) =
                        make_float2(acc[mt][nt][0], acc[mt][nt][1]);
                    *(float2*)(rp + (rbase + 8) * 20 + col) =
                        make_float2(acc[mt][nt][2], acc[mt][nt][3]);
                }
            }
        }
        __syncthreads();

        // ---- reduce 4 partials -> gates in sm_r[0] ----
        {
            int r = tid >> 2, b4 = tid & 3;
            float* rp0 = smf + OFF_R / 4;
            float4 s0 = *(float4*)(rp0 + (0 * 64 + r) * 20 + b4 * 4);
            float4 s1 = *(float4*)(rp0 + (1 * 64 + r) * 20 + b4 * 4);
            float4 s2 = *(float4*)(rp0 + (2 * 64 + r) * 20 + b4 * 4);
            float4 s3 = *(float4*)(rp0 + (3 * 64 + r) * 20 + b4 * 4);
            *(float4*)(rp0 + r * 20 + b4 * 4) =
                make_float4(s0.x + s1.x + s2.x + s3.x,
                            s0.y + s1.y + s2.y + s3.y,
                            s0.z + s1.z + s2.z + s3.z,
                            s0.w + s1.w + s2.w + s3.w);
        }
        __syncthreads();

        // ---- LSTM cell epilogue ----
        {
            const float* gb = smf + OFF_R / 4;
            float xi = gb[( 0 + ehl) * 20 + ebl] + sm_bias[ 0 + ehl];
            float xf = gb[(16 + ehl) * 20 + ebl] + sm_bias[16 + ehl];
            float xg = gb[(32 + ehl) * 20 + ebl] + sm_bias[32 + ehl];
            float xo = gb[(48 + ehl) * 20 + ebl] + sm_bias[48 + ehl];
            float ei = ex2f(-xi * L2E);
            float ef = ex2f(-xf * L2E);
            float eo = ex2f(-xo * L2E);
            float eg = ex2f(-2.f * xg * L2E);
            float di = 1.f + ei, df = 1.f + ef, dc = 1.f + eo, dg = 1.f + eg;
            float q0 = rcpf(di * df);
            float ii = q0 * df, ff = q0 * di;
            float q1 = rcpf(dc * dg);
            float oo = q1 * dg;
            float tg = (1.f - eg) * (q1 * dc);
            c_reg = ff * c_reg + ii * tg;
            float ec = ex2f(-2.f * c_reg * L2E);
            float tc = (1.f - ec) * rcpf(1.f + ec);
            float h  = oo * tc;
            g_hpk[(((size_t)(t + 1) * NG + g) * 16 + ebl) * 512 + c * 16 + ehl] =
                packhl(h);
        }
        __syncthreads();
        if (tid == 0) publish(&g_flags[cta * 32], base + (unsigned)t + 2);
    }

    // ================= conv tail =================
    if (tid < 32)
        poll_flag_sleep(&g_flags[(g * 32 + tid) * 32], base + Tn + 1);
    __syncthreads();

    float* scw  = smf + OFF_BHI / 4;      // reuse B tiles
    float* sred = scw + 512;
    for (int i = tid; i < Hn; i += NTHR) scw[i] = cw[i];
    const float cbv = cb[0];
    __syncthreads();

    const int cb2 = tid >> 4, cs = tid & 15;
    for (int j = 0; j < Tn / GC; ++j) {
        int t = c * (Tn / GC) + j;
        const unsigned* hp =
            g_hpk + (((size_t)(t + 1) * NG + g) * 16 + cb2) * 512 + cs * 32;
        float acc = 0.f;
        #pragma unroll 8
        for (int h = 0; h < 32; ++h) {
            unsigned w = __ldcg(hp + h);
            float hv = __uint_as_float(w << 16) +
                       __uint_as_float(w & 0xFFFF0000u);
            acc += hv * scw[cs * 32 + h];
        }
        sred[tid] = acc;
        __syncthreads();
        if (tid < 16) {
            float s = cbv;
            #pragma unroll
            for (int q = 0; q < 16; ++q) s += sred[tid * 16 + q];
            out[(size_t)(g * 16 + tid) * Tn + t] = s;
        }
        __syncthreads();
    }
}

// ---------------------------------------------------------------------------
extern "C" void kernel_launch(void* const* d_in, const int* in_sizes, int n_in,
                              void* d_out, int out_size)
{
    const float* x    = (const float*)d_in[0];
    const float* W_ih = (const float*)d_in[1];
    const float* W_hh = (const float*)d_in[2];
    const float* b_ih = (const float*)d_in[3];
    const float* b_hh = (const float*)d_in[4];
    const float* cw   = (const float*)d_in[5];
    const float* cb   = (const float*)d_in[6];
    float* out = (float*)d_out;

    cudaFuncSetAttribute(lstm_hmma_kernel,
                         cudaFuncAttributeMaxDynamicSharedMemorySize, SMEM_TOTAL);
    lstm_hmma_kernel<<<NCTA, NTHR, SMEM_TOTAL>>>(x, W_ih, W_hh, b_ih, b_hh,
                                                 cw, cb, out);
}

// round 17
// speedup vs baseline: 1.2955x; 1.0245x over previous
#include <cuda_runtime.h>
#include <cuda_bf16.h>
#include <cstdint>

// Problem constants
#define Tn   1024
#define Bn   64
#define Dn   32
#define Hn   512
#define NG   4              // independent batch groups
#define GC   32             // CTAs per group
#define NCTA 128
#define NTHR 256

// Device-global scratch
// h history, packed u32: low16 = bf16(hi), high16 = bf16(lo)
__device__ unsigned g_hpk[(size_t)(Tn + 1) * NG * 16 * 512];  // [t][g][b][k]
__device__ unsigned g_xpk[(size_t)Tn * NG * 16 * 32];         // [t][g][b][d]
__device__ __align__(128) unsigned g_flags[NCTA * 32];        // 1 flag / 128B line

// SMEM layout (bytes)
#define OFF_BIAS  0                     // 64 floats
#define OFF_BHI   256
#define TILE_B    17408                 // 34 ksteps x 512B (nt-interleaved)
#define OFF_BLO   (OFF_BHI + TILE_B)    // 17664
#define OFF_R     (OFF_BLO + TILE_B)    // 35072: 2 parts x 64 r x 20 floats
#define SMEM_TOTAL (OFF_R + 2 * 64 * 20 * 4)   // 45312

#define L2E 1.4426950408889634f

__device__ __forceinline__ float ex2f(float x) {
    float y; asm("ex2.approx.ftz.f32 %0, %1;" : "=f"(y) : "f"(x)); return y;
}
__device__ __forceinline__ float rcpf(float x) {
    float y; asm("rcp.approx.ftz.f32 %0, %1;" : "=f"(y) : "f"(x)); return y;
}
// pack fp32 -> {bf16 hi | bf16 lo << 16}
__device__ __forceinline__ unsigned packhl(float v) {
    unsigned hb = (unsigned)__bfloat16_as_ushort(__float2bfloat16(v));
    float hf = __uint_as_float(hb << 16);
    unsigned lb = (unsigned)__bfloat16_as_ushort(__float2bfloat16(v - hf));
    return hb | (lb << 16);
}
__device__ __forceinline__ void sts64(uint32_t a, uint32_t x, uint32_t y) {
    asm volatile("st.shared.v2.b32 [%0], {%1,%2};" :: "r"(a), "r"(x), "r"(y));
}
__device__ __forceinline__ void lds128(uint32_t* r, uint32_t a) {
    asm volatile("ld.shared.v4.b32 {%0,%1,%2,%3}, [%4];"
                 : "=r"(r[0]), "=r"(r[1]), "=r"(r[2]), "=r"(r[3]) : "r"(a));
}
__device__ __forceinline__ void poll_flag_sleep(const unsigned* fptr,
                                                unsigned tgt) {
    for (;;) {
        unsigned v;
        asm volatile("ld.acquire.gpu.global.u32 %0, [%1];"
                     : "=r"(v) : "l"(fptr) : "memory");
        if (!__any_sync(0xFFFFFFFFu, (int)(v - tgt) < 0)) break;
        __nanosleep(32);
    }
}
__device__ __forceinline__ void publish(unsigned* flag, unsigned val) {
    asm volatile("st.release.gpu.global.u32 [%0], %1;"
                 :: "l"(flag), "r"(val) : "memory");
}
// m16n8k16 bf16 mma, fp32 acc (HMMA, valid on base sm_103 target)
#define MMA16816(C, A, B0, B1)                                               \
    asm volatile(                                                            \
        "mma.sync.aligned.m16n8k16.row.col.f32.bf16.bf16.f32 "               \
        "{%0,%1,%2,%3}, {%4,%5,%6,%7}, {%8,%9}, {%0,%1,%2,%3};"              \
        : "+f"((C)[0]), "+f"((C)[1]), "+f"((C)[2]), "+f"((C)[3])             \
        : "r"((A)[0]), "r"((A)[1]), "r"((A)[2]), "r"((A)[3]),                \
          "r"(B0), "r"(B1))

// bf16 bits of A'(row, col): row<64 -> hi(W[row]), row>=64 -> lo(W[row-64])
__device__ __forceinline__ unsigned wbits(const float* __restrict__ Whh,
                                          const float* __restrict__ Wih,
                                          int c, int row, int col) {
    int r = row & 63;
    int n = (r >> 4) * Hn + c * 16 + (r & 15);
    float w = (col < 512) ? Whh[(size_t)n * Hn + col]
                          : Wih[n * Dn + (col - 512)];
    unsigned hb = (unsigned)__bfloat16_as_ushort(__float2bfloat16(w));
    if (row < 64) return hb;
    float hf = __uint_as_float(hb << 16);
    return (unsigned)__bfloat16_as_ushort(__float2bfloat16(w - hf));
}

extern __shared__ char smem[];

// ===========================================================================
__global__ void __launch_bounds__(NTHR, 1) lstm_hmma_kernel(
    const float* __restrict__ x,      // (B, D, T)
    const float* __restrict__ W_ih,   // (4H, D)
    const float* __restrict__ W_hh,   // (4H, H)
    const float* __restrict__ b_ih,   // (4H,)
    const float* __restrict__ b_hh,   // (4H,)
    const float* __restrict__ cw,     // (1, H, 1)
    const float* __restrict__ cb,     // (1,)
    float* __restrict__ out)          // (B, 1, T)
{
    const int tid  = threadIdx.x;
    const int cta  = blockIdx.x;
    const int g    = cta >> 5;
    const int c    = cta & 31;
    const int wid  = tid >> 5, lane = tid & 31;
    const int ms   = wid & 3;          // M-slice: 16 rows within hi / lo
    const int kh   = wid >> 2;         // K-half (17 ksteps each)
    const int fg   = lane >> 2;        // fragment group id
    const int ft   = lane & 3;         // fragment thread-in-group
    const uint32_t sb = (uint32_t)__cvta_generic_to_shared(smem);
    float* smf     = (float*)smem;
    float* sm_bias = smf + OFF_BIAS / 4;

    const unsigned base = g_flags[cta * 32];

    // ---- preamble: pack x (B,D,T) -> g_xpk[t][g][b][d]; this CTA's 1/128 ----
    {
        const float4* x4 = (const float4*)x;
        for (int i = tid; i < 4096; i += NTHR) {
            int idx4 = cta * 4096 + i;
            float4 v = __ldcg(x4 + idx4);
            int t0 = (idx4 & 255) * 4;
            int d  = (idx4 >> 8) & 31;
            int b  = idx4 >> 13;
            unsigned* dst = g_xpk + ((b >> 4) * 16 + (b & 15)) * 32 + d;
            dst[(size_t)(t0 + 0) * 2048] = packhl(v.x);
            dst[(size_t)(t0 + 1) * 2048] = packhl(v.y);
            dst[(size_t)(t0 + 2) * 2048] = packhl(v.z);
            dst[(size_t)(t0 + 3) * 2048] = packhl(v.w);
        }
    }
    // zero own h(0)
    g_hpk[((size_t)g * 16 + (tid >> 4)) * 512 + c * 16 + (tid & 15)] = 0u;
    if (tid < 64) {
        int n = (tid >> 4) * Hn + c * 16 + (tid & 15);
        sm_bias[tid] = b_ih[n] + b_hh[n];
    }

    // ---- A fragments into registers: a[mt][ks][rg] ----
    // mt=0: hi rows 16ms..16ms+15; mt=1: lo rows 64+16ms..64+16ms+15
    unsigned a[2][17][4];
    #pragma unroll
    for (int mt = 0; mt < 2; ++mt) {
        #pragma unroll
        for (int ks = 0; ks < 17; ++ks) {
            #pragma unroll
            for (int rg = 0; rg < 4; ++rg) {
                int row = 64 * mt + 16 * ms + fg + (rg & 1) * 8;
                int col = 272 * kh + 16 * ks + 2 * ft + (rg >> 1) * 8;
                unsigned w0 = wbits(W_hh, W_ih, c, row, col);
                unsigned w1 = wbits(W_hh, W_ih, c, row, col + 1);
                a[mt][ks][rg] = w0 | (w1 << 16);
            }
        }
    }

    __syncthreads();
    if (tid == 0) publish(&g_flags[cta * 32], base + 1);
    if (tid < 128) poll_flag_sleep(&g_flags[tid * 32], base + 1);
    __syncthreads();

    // epilogue mapping
    const int ebl = tid & 15, ehl = tid >> 4;
    float c_reg = 0.f;

    // staging: thread stages source ksteps sks0, sks1
    const int sks0 = tid >> 4;            // 0..15
    const int sks1 = 16 + (tid >> 4);     // 16..31
    const unsigned* fp0 = &g_flags[(g * 32 + sks0) * 32];
    const unsigned* fp1 = &g_flags[(g * 32 + sks1) * 32];

    // nt-interleaved B layout: addr = ks*512 + (fg*4+ft)*16 + nt*8
    const uint32_t bhib = sb + OFF_BHI + (kh * 17) * 512 + lane * 16;
    const uint32_t blob = sb + OFF_BLO + (kh * 17) * 512 + lane * 16;

    for (int t = 0; t < Tn; ++t) {
        // ---- stage x slice first (no flag dependency) ----
        if (tid < 32) {
            int aa = tid + 512;
            int ks = aa >> 4, b = aa & 15;        // ks in {32,33}
            const uint4* src = (const uint4*)
                (g_xpk + ((size_t)t * NG + g) * 512 + b * 32 + (ks - 32) * 16);
            uint4 q0 = __ldcg(src + 0), q1 = __ldcg(src + 1);
            uint4 q2 = __ldcg(src + 2), q3 = __ldcg(src + 3);
            unsigned w[16] = {q0.x, q0.y, q0.z, q0.w, q1.x, q1.y, q1.z, q1.w,
                              q2.x, q2.y, q2.z, q2.w, q3.x, q3.y, q3.z, q3.w};
            int nt = b >> 3, g2 = b & 7;
            uint32_t bh = sb + OFF_BHI + ks * 512 + g2 * 64 + nt * 8;
            uint32_t bl = sb + OFF_BLO + ks * 512 + g2 * 64 + nt * 8;
            #pragma unroll
            for (int t4 = 0; t4 < 4; ++t4) {
                sts64(bh + t4 * 16,
                      __byte_perm(w[2 * t4],     w[2 * t4 + 1], 0x5410),
                      __byte_perm(w[2 * t4 + 8], w[2 * t4 + 9], 0x5410));
                sts64(bl + t4 * 16,
                      __byte_perm(w[2 * t4],     w[2 * t4 + 1], 0x7632),
                      __byte_perm(w[2 * t4 + 8], w[2 * t4 + 9], 0x7632));
            }
        }
        // ---- fused dual-flag poll ----
        {
            const unsigned tgt = base + (unsigned)t + 1;
            unsigned v0, v1;
            do {
                asm volatile("ld.acquire.gpu.global.u32 %0, [%1];"
                             : "=r"(v0) : "l"(fp0) : "memory");
                asm volatile("ld.acquire.gpu.global.u32 %0, [%1];"
                             : "=r"(v1) : "l"(fp1) : "memory");
            } while (((int)(v0 - tgt) < 0) | ((int)(v1 - tgt) < 0));
            __syncwarp();
        }
        // ---- stage h tiles (2 slices per thread, split hi/lo) ----
        #pragma unroll
        for (int ai = 0; ai < 2; ++ai) {
            int aa = tid + ai * 256;
            int ks = aa >> 4, b = aa & 15;
            const uint4* src = (const uint4*)
                (g_hpk + ((size_t)t * NG + g) * 8192 + b * 512 + ks * 16);
            uint4 q0 = __ldcg(src + 0), q1 = __ldcg(src + 1);
            uint4 q2 = __ldcg(src + 2), q3 = __ldcg(src + 3);
            unsigned w[16] = {q0.x, q0.y, q0.z, q0.w, q1.x, q1.y, q1.z, q1.w,
                              q2.x, q2.y, q2.z, q2.w, q3.x, q3.y, q3.z, q3.w};
            int nt = b >> 3, g2 = b & 7;
            uint32_t bh = sb + OFF_BHI + ks * 512 + g2 * 64 + nt * 8;
            uint32_t bl = sb + OFF_BLO + ks * 512 + g2 * 64 + nt * 8;
            #pragma unroll
            for (int t4 = 0; t4 < 4; ++t4) {
                sts64(bh + t4 * 16,
                      __byte_perm(w[2 * t4],     w[2 * t4 + 1], 0x5410),
                      __byte_perm(w[2 * t4 + 8], w[2 * t4 + 9], 0x5410));
                sts64(bl + t4 * 16,
                      __byte_perm(w[2 * t4],     w[2 * t4 + 1], 0x7632),
                      __byte_perm(w[2 * t4 + 8], w[2 * t4 + 9], 0x7632));
            }
        }
        __syncthreads();

        // ---- pass 1: B_hi x (A_hi + A_lo), 17 ksteps ----
        float acc[2][2][4];
        #pragma unroll
        for (int mt = 0; mt < 2; ++mt)
            #pragma unroll
            for (int nt = 0; nt < 2; ++nt)
                #pragma unroll
                for (int j = 0; j < 4; ++j) acc[mt][nt][j] = 0.f;

        #pragma unroll
        for (int ks = 0; ks < 17; ++ks) {
            uint32_t bh[4];
            lds128(bh, bhib + ks * 512);
            MMA16816(acc[0][0], a[0][ks], bh[0], bh[1]);
            MMA16816(acc[0][1], a[0][ks], bh[2], bh[3]);
            MMA16816(acc[1][0], a[1][ks], bh[0], bh[1]);
            MMA16816(acc[1][1], a[1][ks], bh[2], bh[3]);
        }
        // ---- pass 2: B_lo x A_hi only (drop lo*lo) ----
        #pragma unroll
        for (int ks = 0; ks < 17; ++ks) {
            uint32_t bl[4];
            lds128(bl, blob + ks * 512);
            MMA16816(acc[0][0], a[0][ks], bl[0], bl[1]);
            MMA16816(acc[0][1], a[0][ks], bl[2], bl[3]);
        }

        // ---- in-register mt merge + store partials (part = kh) ----
        {
            int rbase = 16 * ms + fg;
            float* rp = smf + OFF_R / 4 + kh * 64 * 20;
            #pragma unroll
            for (int nt = 0; nt < 2; ++nt) {
                int col = 8 * nt + 2 * ft;
                *(float2*)(rp + rbase * 20 + col) =
                    make_float2(acc[0][nt][0] + acc[1][nt][0],
                                acc[0][nt][1] + acc[1][nt][1]);
                *(float2*)(rp + (rbase + 8) * 20 + col) =
                    make_float2(acc[0][nt][2] + acc[1][nt][2],
                                acc[0][nt][3] + acc[1][nt][3]);
            }
        }
        __syncthreads();

        // ---- reduce 2 partials -> gates in sm_r[0] ----
        {
            int r = tid >> 2, b4 = tid & 3;
            float* rp0 = smf + OFF_R / 4;
            float4 s0 = *(float4*)(rp0 + (0 * 64 + r) * 20 + b4 * 4);
            float4 s1 = *(float4*)(rp0 + (1 * 64 + r) * 20 + b4 * 4);
            *(float4*)(rp0 + r * 20 + b4 * 4) =
                make_float4(s0.x + s1.x, s0.y + s1.y,
                            s0.z + s1.z, s0.w + s1.w);
        }
        __syncthreads();

        // ---- LSTM cell epilogue ----
        {
            const float* gb = smf + OFF_R / 4;
            float xi = gb[( 0 + ehl) * 20 + ebl] + sm_bias[ 0 + ehl];
            float xf = gb[(16 + ehl) * 20 + ebl] + sm_bias[16 + ehl];
            float xg = gb[(32 + ehl) * 20 + ebl] + sm_bias[32 + ehl];
            float xo = gb[(48 + ehl) * 20 + ebl] + sm_bias[48 + ehl];
            float ei = ex2f(-xi * L2E);
            float ef = ex2f(-xf * L2E);
            float eo = ex2f(-xo * L2E);
            float eg = ex2f(-2.f * xg * L2E);
            float di = 1.f + ei, df = 1.f + ef, dc = 1.f + eo, dg = 1.f + eg;
            float q0 = rcpf(di * df);
            float ii = q0 * df, ff = q0 * di;
            float q1 = rcpf(dc * dg);
            float oo = q1 * dg;
            float tg = (1.f - eg) * (q1 * dc);
            c_reg = ff * c_reg + ii * tg;
            float ec = ex2f(-2.f * c_reg * L2E);
            float tc = (1.f - ec) * rcpf(1.f + ec);
            float h  = oo * tc;
            g_hpk[(((size_t)(t + 1) * NG + g) * 16 + ebl) * 512 + c * 16 + ehl] =
                packhl(h);
        }
        __syncthreads();
        if (tid == 0) publish(&g_flags[cta * 32], base + (unsigned)t + 2);
    }

    // ================= conv tail =================
    if (tid < 32)
        poll_flag_sleep(&g_flags[(g * 32 + tid) * 32], base + Tn + 1);
    __syncthreads();

    float* scw  = smf + OFF_BHI / 4;      // reuse B tiles
    float* sred = scw + 512;
    for (int i = tid; i < Hn; i += NTHR) scw[i] = cw[i];
    const float cbv = cb[0];
    __syncthreads();

    const int cb2 = tid >> 4, cs = tid & 15;
    for (int j = 0; j < Tn / GC; ++j) {
        int t = c * (Tn / GC) + j;
        const unsigned* hp =
            g_hpk + (((size_t)(t + 1) * NG + g) * 16 + cb2) * 512 + cs * 32;
        float acc = 0.f;
        #pragma unroll 8
        for (int h = 0; h < 32; ++h) {
            unsigned w = __ldcg(hp + h);
            float hv = __uint_as_float(w << 16) +
                       __uint_as_float(w & 0xFFFF0000u);
            acc += hv * scw[cs * 32 + h];
        }
        sred[tid] = acc;
        __syncthreads();
        if (tid < 16) {
            float s = cbv;
            #pragma unroll
            for (int q = 0; q < 16; ++q) s += sred[tid * 16 + q];
            out[(size_t)(g * 16 + tid) * Tn + t] = s;
        }
        __syncthreads();
    }
}

// ---------------------------------------------------------------------------
extern "C" void kernel_launch(void* const* d_in, const int* in_sizes, int n_in,
                              void* d_out, int out_size)
{
    const float* x    = (const float*)d_in[0];
    const float* W_ih = (const float*)d_in[1];
    const float* W_hh = (const float*)d_in[2];
    const float* b_ih = (const float*)d_in[3];
    const float* b_hh = (const float*)d_in[4];
    const float* cw   = (const float*)d_in[5];
    const float* cb   = (const float*)d_in[6];
    float* out = (float*)d_out;

    cudaFuncSetAttribute(lstm_hmma_kernel,
                         cudaFuncAttributeMaxDynamicSharedMemorySize, SMEM_TOTAL);
    lstm_hmma_kernel<<<NCTA, NTHR, SMEM_TOTAL>>>(x, W_ih, W_hh, b_ih, b_hh,
                                                 cw, cb, out);
}